// round 16
// baseline (speedup 1.0000x reference)
#include <cuda_runtime.h>
#include <cuda_bf16.h>
#include <math.h>
#include <stdint.h>

#define NN    50000
#define MPAD  50048
#define NE    320000
#define D_IN  128
#define D_OUT 256
#define D_HID 512

// ---------------- scratch (per-pass duplicated; no allocation) ----------------
__device__ __nv_bfloat16 g_Hb[2][(size_t)MPAD * D_OUT];
__device__ __nv_bfloat16 g_Tb[2][(size_t)MPAD * D_HID];
__device__ __nv_bfloat16 g_Ub[2][(size_t)MPAD * D_OUT];
__device__ float  g_Uf [2][(size_t)NN * D_OUT];
__device__ float  g_RE1[(size_t)NN * D_IN];
__device__ float  g_RE2[(size_t)NN * D_IN];
__device__ __nv_bfloat16 g_WTb[655360];
__device__ double g_sum[12 * D_HID];     // single-use stat buffers (zeroed once/replay)
__device__ double g_sq [12 * D_HID];
__device__ int    g_ctr[12];             // per-GEMM CTA-completion counters
__device__ float  g_mean[2 * D_HID];     // per-pass BN params (for aggregates/bncos)
__device__ float  g_rstd[2 * D_HID];
__device__ float2 g_scsh[2][D_HID];      // per-pass combined (scale, shift) for GEMM-fused BN
__device__ double g_acc[8];

// per-pass CSR
__device__ int g_deg   [2][NN];
__device__ int g_rowptr[2][NN + 1];
__device__ int g_cursor[2][NN];
__device__ int g_col   [2][NE];

__device__ int g_mask_mode, g_ei_i64, g_cnt[8];

// ---------------- dtype detection ----------------
__global__ void k_zero_cnt() { if (threadIdx.x < 8) g_cnt[threadIdx.x] = 0; }

__global__ void k_detect(const unsigned char* __restrict__ mbytes,
                         const int* __restrict__ eints) {
    int i  = blockIdx.x * blockDim.x + threadIdx.x;
    int st = gridDim.x * blockDim.x;
    int c1 = 0, c3 = 0, ez = 0;
    for (int j = i; j < NN; j += st) {
        unsigned char v = mbytes[j];
        if (v && (j & 3) == 1) c1++;
        if (v && (j & 3) == 3) c3++;
    }
    for (int j = i; j < 100000; j += st)
        if ((j & 1) && eints[j] == 0) ez++;
    atomicAdd(&g_cnt[0], c1);
    atomicAdd(&g_cnt[1], c3);
    atomicAdd(&g_cnt[2], ez);
}

__global__ void k_detect_fin() {
    if (threadIdx.x == 0) {
        if      (g_cnt[1] > 1000) g_mask_mode = 2;
        else if (g_cnt[0] > 1000) g_mask_mode = 0;
        else                      g_mask_mode = 1;
        g_ei_i64 = (g_cnt[2] > 25000) ? 1 : 0;
    }
}

__device__ __forceinline__ bool mask_at(const void* __restrict__ m, int n) {
    int mode = g_mask_mode;
    if (mode == 0) return ((const unsigned char*)m)[n] != 0;
    if (mode == 1) return ((const int*)m)[n] != 0;
    return ((const float*)m)[n] != 0.f;
}

__device__ __forceinline__ int ei_at(const void* __restrict__ ei, long idx) {
    return g_ei_i64 ? (int)((const long long*)ei)[idx] : ((const int*)ei)[idx];
}

// ---------------- per-replay zeroing: loss acc, stat buffers, counters, degrees ----------------
__global__ void k_zero_acc() {
    if (threadIdx.x < 8 && blockIdx.x == 0) g_acc[threadIdx.x] = 0.0;
    if (threadIdx.x < 12 && blockIdx.x == 1) g_ctr[threadIdx.x] = 0;
    int c  = blockIdx.x * blockDim.x + threadIdx.x;
    int st = gridDim.x * blockDim.x;
    for (int i = c; i < 12 * D_HID; i += st) { g_sum[i] = 0.0; g_sq[i] = 0.0; }
    int* dg = &g_deg[0][0];
    for (int i = c; i < 2 * NN; i += st) dg[i] = 0;
}

// ---------------- weight transpose+convert: W[K][N] f32 -> WT[N][K] bf16 ----------------
__global__ void k_transpose(const float* __restrict__ W, __nv_bfloat16* __restrict__ WT,
                            int K, int N) {
    __shared__ float tile[32][33];
    int n0 = blockIdx.x * 32, k0 = blockIdx.y * 32;
    int tx = threadIdx.x, ty = threadIdx.y;
    #pragma unroll
    for (int i = 0; i < 4; i++)
        tile[ty + i * 8][tx] = W[(size_t)(k0 + ty + i * 8) * N + n0 + tx];
    __syncthreads();
    #pragma unroll
    for (int i = 0; i < 4; i++)
        WT[(size_t)(n0 + ty + i * 8) * K + k0 + tx] = __float2bfloat16(tile[tx][ty + i * 8]);
}

// ---------------- CSR build (parameterized per pass) ----------------
__global__ void k_count(const void* __restrict__ ei, int* __restrict__ deg) {
    int e  = blockIdx.x * blockDim.x + threadIdx.x;
    int st = gridDim.x * blockDim.x;
    for (; e < NE; e += st)
        atomicAdd(&deg[ei_at(ei, (long)NE + e)], 1);
}

__global__ void __launch_bounds__(1024) k_scan(const int* __restrict__ deg,
                                               int* __restrict__ rowptr,
                                               int* __restrict__ cursor) {
    __shared__ int ssum[1024];
    const int t = threadIdx.x;
    const int C = (NN + 1023) / 1024;
    int lo = t * C, hi = min(NN, lo + C);
    int s = 0;
    for (int i = lo; i < hi; i++) s += deg[i];
    ssum[t] = s;
    __syncthreads();
    #pragma unroll
    for (int o = 1; o < 1024; o <<= 1) {
        int v = (t >= o) ? ssum[t - o] : 0;
        __syncthreads();
        ssum[t] += v;
        __syncthreads();
    }
    int run = (t == 0) ? 0 : ssum[t - 1];
    for (int i = lo; i < hi; i++) {
        int d = deg[i];
        rowptr[i] = run;
        cursor[i] = run;
        run += d;
    }
    if (t == 1023) rowptr[NN] = run;
}

__global__ void k_fill(const void* __restrict__ ei, int* __restrict__ cursor,
                       int* __restrict__ col) {
    int e  = blockIdx.x * blockDim.x + threadIdx.x;
    int st = gridDim.x * blockDim.x;
    for (; e < NE; e += st) {
        int s = ei_at(ei, e);
        int d = ei_at(ei, (long)NE + e);
        int slot = atomicAdd(&cursor[d], 1);
        col[slot] = s;
    }
}

// ---------------- bf16 helpers ----------------
__device__ __forceinline__ uint32_t pack_bf16x2(float lo, float hi) {
    uint32_t r;
    asm("cvt.rn.bf16x2.f32 %0, %1, %2;" : "=r"(r) : "f"(hi), "f"(lo));
    return r;
}
__device__ __forceinline__ float bflo(uint32_t u) { return __uint_as_float(u << 16); }
__device__ __forceinline__ float bfhi(uint32_t u) { return __uint_as_float(u & 0xffff0000u); }

// ---- fp32-input CSR aggregate (layer 0): D=128, masked -> bf16 out ----
__global__ void k_aggregate_f(const float* __restrict__ in, __nv_bfloat16* __restrict__ hb,
                              const void* __restrict__ m,
                              const int* __restrict__ rowptr, const int* __restrict__ col) {
    const int gtid = blockIdx.x * blockDim.x + threadIdx.x;
    const int warp = gtid >> 5;
    const int lane = gtid & 31;
    if (warp >= NN) return;
    const float4* ip = (const float4*)in;

    float4 a0 = make_float4(0.f, 0.f, 0.f, 0.f);
    if (!mask_at(m, warp)) a0 = ip[(size_t)warp * 32 + lane];

    int j   = rowptr[warp];
    int end = rowptr[warp + 1];
    for (; j < end; j += 4) {
        int cnt = end - j;
        int idx[4]; bool ok[4];
        #pragma unroll
        for (int t = 0; t < 4; t++) {
            idx[t] = (t < cnt) ? __ldg(&col[j + t]) : 0;
            ok[t]  = (t < cnt) && !mask_at(m, idx[t]);
        }
        float4 v[4];
        #pragma unroll
        for (int t = 0; t < 4; t++)
            if (ok[t]) v[t] = __ldg(&ip[(size_t)idx[t] * 32 + lane]);
        #pragma unroll
        for (int t = 0; t < 4; t++)
            if (ok[t]) { a0.x += v[t].x; a0.y += v[t].y; a0.z += v[t].z; a0.w += v[t].w; }
    }
    uint2* hp = (uint2*)hb;
    hp[(size_t)warp * 32 + lane] = make_uint2(pack_bf16x2(a0.x, a0.y), pack_bf16x2(a0.z, a0.w));
}

// ---- bf16-input CSR aggregate: D=256, fused BN+ReLU (per-pass mean/rstd), opt mask ----
template <bool MASKED>
__global__ void k_aggregate_b(const __nv_bfloat16* __restrict__ in, __nv_bfloat16* __restrict__ hb,
                              const void* __restrict__ m,
                              const float* __restrict__ gg, const float* __restrict__ bb,
                              const int* __restrict__ rowptr, const int* __restrict__ col,
                              int pass) {
    const int gtid = blockIdx.x * blockDim.x + threadIdx.x;
    const int warp = gtid >> 5;
    const int lane = gtid & 31;
    if (warp >= NN) return;
    const uint4* ip = (const uint4*)in;
    const int mo = pass * D_HID;

    float sc[8], sh[8];
    #pragma unroll
    for (int i = 0; i < 8; i++) {
        int ch = lane * 8 + i;
        sc[i] = g_rstd[mo + ch] * __ldg(&gg[ch]);
        sh[i] = __ldg(&bb[ch]) - g_mean[mo + ch] * sc[i];
    }

    float a[8];
    #pragma unroll
    for (int i = 0; i < 8; i++) a[i] = 0.f;

    auto consume = [&](uint4 u) {
        float f[8];
        f[0] = bflo(u.x); f[1] = bfhi(u.x);
        f[2] = bflo(u.y); f[3] = bfhi(u.y);
        f[4] = bflo(u.z); f[5] = bfhi(u.z);
        f[6] = bflo(u.w); f[7] = bfhi(u.w);
        #pragma unroll
        for (int i = 0; i < 8; i++)
            a[i] += fmaxf(f[i] * sc[i] + sh[i], 0.f);
    };

    if (!(MASKED && mask_at(m, warp)))
        consume(ip[(size_t)warp * 32 + lane]);

    int j   = rowptr[warp];
    int end = rowptr[warp + 1];
    for (; j < end; j += 4) {
        int cnt = end - j;
        int idx[4]; bool ok[4];
        #pragma unroll
        for (int t = 0; t < 4; t++) {
            idx[t] = (t < cnt) ? __ldg(&col[j + t]) : 0;
            ok[t]  = (t < cnt) && (!MASKED || !mask_at(m, idx[t]));
        }
        uint4 v[4];
        #pragma unroll
        for (int t = 0; t < 4; t++)
            if (ok[t]) v[t] = __ldg(&ip[(size_t)idx[t] * 32 + lane]);
        #pragma unroll
        for (int t = 0; t < 4; t++)
            if (ok[t]) consume(v[t]);
    }

    uint4* hp = (uint4*)hb;
    hp[(size_t)warp * 32 + lane] = make_uint4(
        pack_bf16x2(a[0], a[1]), pack_bf16x2(a[2], a[3]),
        pack_bf16x2(a[4], a[5]), pack_bf16x2(a[6], a[7]));
}

// ---------------- cp.async helpers ----------------
__device__ __forceinline__ void cp_async16(uint32_t dst, const void* src) {
    asm volatile("cp.async.cg.shared.global [%0], [%1], 16;" :: "r"(dst), "l"(src));
}
__device__ __forceinline__ void cp_commit() { asm volatile("cp.async.commit_group;"); }
template <int W> __device__ __forceinline__ void cp_wait() {
    asm volatile("cp.async.wait_group %0;" :: "n"(W));
}

// ---------------- bf16 mma + ldmatrix ----------------
__device__ __forceinline__ void mma_bf16(float* d, const uint32_t* a, const uint32_t* b) {
    asm volatile(
        "mma.sync.aligned.m16n8k16.row.col.f32.bf16.bf16.f32 "
        "{%0,%1,%2,%3}, {%4,%5,%6,%7}, {%8,%9}, {%0,%1,%2,%3};"
        : "+f"(d[0]), "+f"(d[1]), "+f"(d[2]), "+f"(d[3])
        : "r"(a[0]), "r"(a[1]), "r"(a[2]), "r"(a[3]), "r"(b[0]), "r"(b[1]));
}

__device__ __forceinline__ void ldsm4(uint32_t* r, uint32_t addr) {
    asm volatile("ldmatrix.sync.aligned.m8n8.x4.shared.b16 {%0,%1,%2,%3}, [%4];"
        : "=r"(r[0]), "=r"(r[1]), "=r"(r[2]), "=r"(r[3]) : "r"(addr));
}

// ---------------- 3-stage pipelined bf16 GEMM (128x128, ldmatrix, fused BN on A,
//                   last-CTA fused BN-finalize) ----------------
#define SW 20
#define BUFW (128 * SW)
#define GEMM_DSMEM      (3 * 2 * BUFW * 4)            // 61440 bytes
#define GEMM_DSMEM_BNA  (GEMM_DSMEM + 4096)           // + scale/shift table

// BNA: A holds RAW pre-BN bf16; relu(bn(.)) applied to fragments in registers.
// Epilogue: per-col sum/sumsq -> g_sum/g_sq[sbuf]; the LAST CTA to finish
// computes g_mean/g_rstd[pass] (+ g_scsh[pass] when fgg != null) for channels [0, NOUT).
template <bool WBF16, bool BNA>
__global__ void __launch_bounds__(256)
k_gemm(const __nv_bfloat16* __restrict__ A, const __nv_bfloat16* __restrict__ Bt,
       float* __restrict__ C, __nv_bfloat16* __restrict__ Cb,
       const float2* __restrict__ scsh,
       const float* __restrict__ fgg, const float* __restrict__ fbb,
       int M, int K, int N, int sbuf, int pass) {
    extern __shared__ uint32_t dsm[];
    const uint32_t sbase = (uint32_t)__cvta_generic_to_shared(dsm);
    float2* s_scsh = (float2*)((char*)dsm + GEMM_DSMEM);

    const int tid  = threadIdx.x;
    const int lane = tid & 31;
    const int warp = tid >> 5;
    const int wm   = warp & 3;
    const int wn   = warp >> 2;
    const int gid  = lane >> 2;
    const int tq   = lane & 3;
    const int brow = blockIdx.y * 128;
    const int bcol = blockIdx.x * 128;

    if (BNA) {
        s_scsh[tid]       = scsh[tid];
        s_scsh[tid + 256] = scsh[tid + 256];
    }

    // ldmatrix source byte-offsets, kw=0 basis
    const int tIdx = lane >> 3;
    const int trow = lane & 7;
    uint32_t aoff[2];
    #pragma unroll
    for (int mt = 0; mt < 2; mt++) {
        int row  = wm * 32 + mt * 16 + (tIdx & 1) * 8 + trow;
        int word = (tIdx >> 1) * 4;
        aoff[mt] = (uint32_t)(row * SW + word) * 4;
    }
    uint32_t boff[4];
    #pragma unroll
    for (int j = 0; j < 4; j++) {
        int nt   = 2 * j + (tIdx >> 1);
        int row  = wn * 64 + nt * 8 + trow;
        int word = (tIdx & 1) * 4;
        boff[j]  = (uint32_t)(row * SW + word) * 4;
    }

    float acc[2][8][4];
    #pragma unroll
    for (int i = 0; i < 2; i++)
        #pragma unroll
        for (int j = 0; j < 8; j++)
            #pragma unroll
            for (int q = 0; q < 4; q++) acc[i][j][q] = 0.f;

    const int nch = K >> 5;

    auto fill = [&](int s, int k0) {
        uint32_t abase = sbase + (uint32_t)(s * 2 * BUFW) * 4;
        uint32_t bbase = abase + (uint32_t)BUFW * 4;
        #pragma unroll
        for (int i = 0; i < 2; i++) {
            int idx = tid + i * 256;
            int row = idx >> 2;
            int c16 = idx & 3;
            uint32_t doff = (uint32_t)(row * SW + c16 * 4) * 4;
            cp_async16(abase + doff, A  + (size_t)(brow + row) * K + k0 + c16 * 8);
            cp_async16(bbase + doff, Bt + (size_t)(bcol + row) * K + k0 + c16 * 8);
        }
    };

    fill(0, 0);  cp_commit();
    fill(1, 32); cp_commit();

    for (int c = 0; c < nch; c++) {
        if (c < nch - 1) cp_wait<1>(); else cp_wait<0>();
        __syncthreads();
        if (c + 2 < nch) { fill((c + 2) % 3, (c + 2) << 5); cp_commit(); }

        const uint32_t sA = sbase + (uint32_t)((c % 3) * 2 * BUFW) * 4;
        const uint32_t sB = sA + (uint32_t)BUFW * 4;
        #pragma unroll
        for (int kw = 0; kw < 16; kw += 8) {
            uint32_t a[2][4], bt[4][4];
            ldsm4(a[0], sA + aoff[0] + kw * 4);
            ldsm4(a[1], sA + aoff[1] + kw * 4);
            #pragma unroll
            for (int j = 0; j < 4; j++)
                ldsm4(bt[j], sB + boff[j] + kw * 4);

            if (BNA) {
                int cb = (c << 5) + 2 * kw + 2 * tq;
                float4 p0 = *(const float4*)&s_scsh[cb];
                float4 p1 = *(const float4*)&s_scsh[cb + 8];
                #pragma unroll
                for (int mt = 0; mt < 2; mt++) {
                    #pragma unroll
                    for (int q = 0; q < 4; q++) {
                        float4 p = (q < 2) ? p0 : p1;
                        uint32_t r = a[mt][q];
                        float lo = fmaxf(bflo(r) * p.x + p.y, 0.f);
                        float hi = fmaxf(bfhi(r) * p.z + p.w, 0.f);
                        a[mt][q] = pack_bf16x2(lo, hi);
                    }
                }
            }

            #pragma unroll
            for (int mt = 0; mt < 2; mt++)
                #pragma unroll
                for (int j = 0; j < 4; j++) {
                    mma_bf16(acc[mt][2 * j],     a[mt], &bt[j][0]);
                    mma_bf16(acc[mt][2 * j + 1], a[mt], &bt[j][2]);
                }
        }
        __syncthreads();
    }

    // ---- store C ----
    #pragma unroll
    for (int mt = 0; mt < 2; mt++) {
        int r0 = brow + wm * 32 + mt * 16 + gid;
        int r1 = r0 + 8;
        #pragma unroll
        for (int nt = 0; nt < 8; nt++) {
            int c = bcol + wn * 64 + nt * 8 + tq * 2;
            if (WBF16) {
                if (r0 < M)
                    *(uint32_t*)(Cb + (size_t)r0 * N + c) = pack_bf16x2(acc[mt][nt][0], acc[mt][nt][1]);
                if (r1 < M)
                    *(uint32_t*)(Cb + (size_t)r1 * N + c) = pack_bf16x2(acc[mt][nt][2], acc[mt][nt][3]);
            } else {
                if (r0 < M)
                    *(float2*)(C + (size_t)r0 * N + c) = make_float2(acc[mt][nt][0], acc[mt][nt][1]);
                if (r1 < M)
                    *(float2*)(C + (size_t)r1 * N + c) = make_float2(acc[mt][nt][2], acc[mt][nt][3]);
            }
        }
    }

    // ---- column stats -> buffer sbuf ----
    float csum[16], csq[16];
    #pragma unroll
    for (int nt = 0; nt < 8; nt++) {
        float s0 = 0.f, s1 = 0.f, q0 = 0.f, q1 = 0.f;
        #pragma unroll
        for (int mt = 0; mt < 2; mt++) {
            int r0 = brow + wm * 32 + mt * 16 + gid;
            int r1 = r0 + 8;
            if (r0 < M) {
                float a = acc[mt][nt][0], b = acc[mt][nt][1];
                s0 += a; q0 += a * a; s1 += b; q1 += b * b;
            }
            if (r1 < M) {
                float a = acc[mt][nt][2], b = acc[mt][nt][3];
                s0 += a; q0 += a * a; s1 += b; q1 += b * b;
            }
        }
        csum[nt * 2] = s0; csum[nt * 2 + 1] = s1;
        csq [nt * 2] = q0; csq [nt * 2 + 1] = q1;
    }
    #pragma unroll
    for (int o = 4; o <= 16; o <<= 1) {
        #pragma unroll
        for (int p = 0; p < 16; p++) {
            csum[p] += __shfl_xor_sync(0xffffffffu, csum[p], o);
            csq[p]  += __shfl_xor_sync(0xffffffffu, csq[p],  o);
        }
    }
    float* s_ps = (float*)dsm;
    float* s_pq = s_ps + 512;
    __syncthreads();
    if (gid == 0) {
        #pragma unroll
        for (int nt = 0; nt < 8; nt++) {
            int lc = wn * 64 + nt * 8 + tq * 2;
            s_ps[wm * 128 + lc]     = csum[nt * 2];
            s_ps[wm * 128 + lc + 1] = csum[nt * 2 + 1];
            s_pq[wm * 128 + lc]     = csq[nt * 2];
            s_pq[wm * 128 + lc + 1] = csq[nt * 2 + 1];
        }
    }
    __syncthreads();
    if (tid < 128) {
        float ts = s_ps[tid] + s_ps[128 + tid] + s_ps[256 + tid] + s_ps[384 + tid];
        float tg = s_pq[tid] + s_pq[128 + tid] + s_pq[256 + tid] + s_pq[384 + tid];
        atomicAdd(&g_sum[sbuf * D_HID + bcol + tid], (double)ts);
        atomicAdd(&g_sq [sbuf * D_HID + bcol + tid], (double)tg);
    }

    // ---- last-CTA BN finalize (replaces the k_bn_fin launch) ----
    __syncthreads();
    __shared__ int s_last;
    if (tid == 0) {
        __threadfence();
        int nCTA = gridDim.x * gridDim.y;
        int v = atomicAdd(&g_ctr[sbuf], 1);
        s_last = (v == nCTA - 1);
    }
    __syncthreads();
    if (s_last) {
        __threadfence();   // acquire: see all CTAs' stat atomics
        for (int c2 = tid; c2 < N; c2 += 256) {
            double mu  = g_sum[sbuf * D_HID + c2] / NN;
            double var = g_sq [sbuf * D_HID + c2] / NN - mu * mu;
            if (var < 0.0) var = 0.0;
            float rs = (float)rsqrt(var + 1e-5);
            float mf = (float)mu;
            g_mean[pass * D_HID + c2] = mf;
            g_rstd[pass * D_HID + c2] = rs;
            if (fgg) {
                float s = rs * fgg[c2];
                g_scsh[pass][c2] = make_float2(s, fbb[c2] - mf * s);
            }
        }
        if (fgg) {
            for (int c2 = N + tid; c2 < D_HID; c2 += 256)
                g_scsh[pass][c2] = make_float2(0.f, 0.f);   // pad channels
        }
    }
}

// ---- fused decoder epilogue: RE = relu(bn(U)); masked 1-cos(RE, x) -> g_acc ----
__global__ void k_bncos(const float* __restrict__ U, float* __restrict__ RE,
                        const float* __restrict__ gg, const float* __restrict__ bb,
                        const float* __restrict__ x, const void* __restrict__ m,
                        int pass, int accOff) {
    int gtid = blockIdx.x * blockDim.x + threadIdx.x;
    int warp = gtid >> 5, lane = gtid & 31;
    int nw   = (gridDim.x * blockDim.x) >> 5;
    const int mo = pass * D_HID;

    int ch = lane * 4;
    float4 sc, sh;
    sc.x = g_rstd[mo+ch+0] * __ldg(&gg[ch+0]); sh.x = __ldg(&bb[ch+0]) - g_mean[mo+ch+0]*sc.x;
    sc.y = g_rstd[mo+ch+1] * __ldg(&gg[ch+1]); sh.y = __ldg(&bb[ch+1]) - g_mean[mo+ch+1]*sc.y;
    sc.z = g_rstd[mo+ch+2] * __ldg(&gg[ch+2]); sh.z = __ldg(&bb[ch+2]) - g_mean[mo+ch+2]*sc.z;
    sc.w = g_rstd[mo+ch+3] * __ldg(&gg[ch+3]); sh.w = __ldg(&bb[ch+3]) - g_mean[mo+ch+3]*sc.w;

    double ls = 0.0, lc = 0.0;
    for (int n = warp; n < NN; n += nw) {
        float4 u = *((const float4*)(U + (size_t)n * 128) + lane);
        float4 v;
        v.x = fmaxf(u.x * sc.x + sh.x, 0.f);
        v.y = fmaxf(u.y * sc.y + sh.y, 0.f);
        v.z = fmaxf(u.z * sc.z + sh.z, 0.f);
        v.w = fmaxf(u.w * sc.w + sh.w, 0.f);
        *((float4*)(RE + (size_t)n * 128) + lane) = v;

        if (mask_at(m, n)) {
            float4 vb = *((const float4*)(x + (size_t)n * 128) + lane);
            float dot = v.x*vb.x + v.y*vb.y + v.z*vb.z + v.w*vb.w;
            float na  = v.x*v.x + v.y*v.y + v.z*v.z + v.w*v.w;
            float nb  = vb.x*vb.x + vb.y*vb.y + vb.z*vb.z + vb.w*vb.w;
            #pragma unroll
            for (int o = 16; o; o >>= 1) {
                dot += __shfl_xor_sync(0xffffffffu, dot, o);
                na  += __shfl_xor_sync(0xffffffffu, na,  o);
                nb  += __shfl_xor_sync(0xffffffffu, nb,  o);
            }
            if (lane == 0) {
                float cs = dot / (fmaxf(sqrtf(na), 1e-12f) * fmaxf(sqrtf(nb), 1e-12f));
                ls += 1.0 - (double)cs;
                lc += 1.0;
            }
        }
    }
    if (lane == 0 && lc > 0.0) {
        atomicAdd(&g_acc[accOff], ls);
        atomicAdd(&g_acc[accOff + 1], lc);
    }
}

// ---------------- contrastive cosine (all nodes) ----------------
__global__ void k_cos(const float* __restrict__ a, const float* __restrict__ b,
                      int accOff) {
    int gtid = blockIdx.x * blockDim.x + threadIdx.x;
    int warp = gtid >> 5, lane = gtid & 31;
    int nw   = (gridDim.x * blockDim.x) >> 5;
    double ls = 0.0;
    for (int n = warp; n < NN; n += nw) {
        float4 va = *((const float4*)(a + (size_t)n * 128) + lane);
        float4 vb = *((const float4*)(b + (size_t)n * 128) + lane);
        float dot = va.x*vb.x + va.y*vb.y + va.z*vb.z + va.w*vb.w;
        float na  = va.x*va.x + va.y*va.y + va.z*va.z + va.w*va.w;
        float nb  = vb.x*vb.x + vb.y*vb.y + vb.z*vb.z + vb.w*vb.w;
        #pragma unroll
        for (int o = 16; o; o >>= 1) {
            dot += __shfl_xor_sync(0xffffffffu, dot, o);
            na  += __shfl_xor_sync(0xffffffffu, na,  o);
            nb  += __shfl_xor_sync(0xffffffffu, nb,  o);
        }
        if (lane == 0) {
            float cs = dot / (fmaxf(sqrtf(na), 1e-12f) * fmaxf(sqrtf(nb), 1e-12f));
            ls += 1.0 - (double)cs;
        }
    }
    if (lane == 0) atomicAdd(&g_acc[accOff], ls);
}

__global__ void k_finalize(float* out) {
    double v = g_acc[0] / g_acc[1] + g_acc[2] / g_acc[3] + 0.1 * (g_acc[4] / (double)NN);
    out[0] = (float)v;
}

// ---------------- host-side orchestration ----------------
extern "C" void kernel_launch(void* const* d_in, const int* in_sizes, int n_in,
                              void* d_out, int out_size) {
    const float* x   = (const float*)d_in[0];
    const void*  eis[2] = { d_in[1], d_in[2] };
    const void*  ms [2] = { d_in[3], d_in[4] };
    const float* e0_w1 = (const float*)d_in[6];
    const float* e0_w2 = (const float*)d_in[7];
    const float* e0_bg = (const float*)d_in[8];
    const float* e0_bb = (const float*)d_in[9];
    const float* e0_ng = (const float*)d_in[10];
    const float* e0_nb = (const float*)d_in[11];
    const float* e1_w1 = (const float*)d_in[12];
    const float* e1_w2 = (const float*)d_in[13];
    const float* e1_bg = (const float*)d_in[14];
    const float* e1_bb = (const float*)d_in[15];
    const float* e1_ng = (const float*)d_in[16];
    const float* e1_nb = (const float*)d_in[17];
    const float* d_w1  = (const float*)d_in[18];
    const float* d_w2  = (const float*)d_in[19];
    const float* d_bg  = (const float*)d_in[20];
    const float* d_bb  = (const float*)d_in[21];
    const float* d_ng  = (const float*)d_in[22];
    const float* d_nb  = (const float*)d_in[23];
    float* out = (float*)d_out;

    __nv_bfloat16 *Hb0, *Tb0, *Ub0, *WTb;
    float *Uf0, *RE1, *RE2;
    float2* scsh0;
    int *deg0, *rp0, *cur0, *col0;
    cudaGetSymbolAddress((void**)&Hb0, g_Hb);
    cudaGetSymbolAddress((void**)&Tb0, g_Tb);
    cudaGetSymbolAddress((void**)&Ub0, g_Ub);
    cudaGetSymbolAddress((void**)&WTb, g_WTb);
    cudaGetSymbolAddress((void**)&Uf0, g_Uf);
    cudaGetSymbolAddress((void**)&RE1, g_RE1);
    cudaGetSymbolAddress((void**)&RE2, g_RE2);
    cudaGetSymbolAddress((void**)&scsh0, g_scsh);
    cudaGetSymbolAddress((void**)&deg0, g_deg);
    cudaGetSymbolAddress((void**)&rp0,  g_rowptr);
    cudaGetSymbolAddress((void**)&cur0, g_cursor);
    cudaGetSymbolAddress((void**)&col0, g_col);

    __nv_bfloat16* Hb[2] = { Hb0, Hb0 + (size_t)MPAD * D_OUT };
    __nv_bfloat16* Tb[2] = { Tb0, Tb0 + (size_t)MPAD * D_HID };
    __nv_bfloat16* Ub[2] = { Ub0, Ub0 + (size_t)MPAD * D_OUT };
    float*         Uf[2] = { Uf0, Uf0 + (size_t)NN * D_OUT };
    float*         RE[2] = { RE1, RE2 };
    float2*      scsh[2] = { scsh0, scsh0 + D_HID };
    int* deg[2] = { deg0, deg0 + NN };
    int* rp [2] = { rp0,  rp0 + NN + 1 };
    int* cur[2] = { cur0, cur0 + NN };
    int* col[2] = { col0, col0 + NE };

    __nv_bfloat16* WT0 = WTb;
    __nv_bfloat16* WT1 = WTb + 65536;
    __nv_bfloat16* WT2 = WTb + 196608;
    __nv_bfloat16* WT3 = WTb + 327680;
    __nv_bfloat16* WT4 = WTb + 458752;
    __nv_bfloat16* WT5 = WTb + 589824;

    static cudaStream_t st[2] = { nullptr, nullptr };
    static cudaEvent_t  evR = nullptr, evJ0 = nullptr, evJ1 = nullptr;
    if (!st[0]) {
        cudaStreamCreateWithFlags(&st[0], cudaStreamNonBlocking);
        cudaStreamCreateWithFlags(&st[1], cudaStreamNonBlocking);
        cudaEventCreateWithFlags(&evR,  cudaEventDisableTiming);
        cudaEventCreateWithFlags(&evJ0, cudaEventDisableTiming);
        cudaEventCreateWithFlags(&evJ1, cudaEventDisableTiming);
        cudaFuncSetAttribute(k_gemm<true,  false>, cudaFuncAttributeMaxDynamicSharedMemorySize, GEMM_DSMEM);
        cudaFuncSetAttribute(k_gemm<false, false>, cudaFuncAttributeMaxDynamicSharedMemorySize, GEMM_DSMEM);
        cudaFuncSetAttribute(k_gemm<true,  true>,  cudaFuncAttributeMaxDynamicSharedMemorySize, GEMM_DSMEM_BNA);
        cudaFuncSetAttribute(k_gemm<false, true>,  cudaFuncAttributeMaxDynamicSharedMemorySize, GEMM_DSMEM_BNA);
    }

    // ---- prelude on default stream ----
    k_zero_cnt<<<1, 32>>>();
    k_detect<<<128, 256>>>((const unsigned char*)ms[0], (const int*)eis[0]);
    k_detect_fin<<<1, 32>>>();
    k_zero_acc<<<48, 256>>>();

    dim3 tb(32, 8);
    k_transpose<<<dim3(512/32, 128/32), tb>>>(e0_w1, WT0, 128, 512);
    k_transpose<<<dim3(256/32, 512/32), tb>>>(e0_w2, WT1, 512, 256);
    k_transpose<<<dim3(512/32, 256/32), tb>>>(e1_w1, WT2, 256, 512);
    k_transpose<<<dim3(256/32, 512/32), tb>>>(e1_w2, WT3, 512, 256);
    k_transpose<<<dim3(512/32, 256/32), tb>>>(d_w1,  WT4, 256, 512);
    k_transpose<<<dim3(128/32, 512/32), tb>>>(d_w2,  WT5, 512, 128);

    // ---- fork ----
    cudaEventRecord(evR, 0);
    cudaStreamWaitEvent(st[0], evR, 0);
    cudaStreamWaitEvent(st[1], evR, 0);

    const int AGG_BLK = (NN * 32 + 255) / 256;
    const dim3 gN512(4, MPAD / 128);
    const dim3 gN256(2, MPAD / 128);
    const dim3 gN128(1, MPAD / 128);

    for (int p = 0; p < 2; p++) {
        cudaStream_t S = st[p];
        const void* ei = eis[p];
        const void* m  = ms[p];
        const int   sb = p * 6;

        k_count<<<1024, 256, 0, S>>>(ei, deg[p]);
        k_scan<<<1, 1024, 0, S>>>(deg[p], rp[p], cur[p]);
        k_fill<<<1024, 256, 0, S>>>(ei, cur[p], col[p]);

        // encoder layer 0: agg -> GEMM1(raw Tb + stats + fin/scsh) -> GEMM2(fused BN on A)
        k_aggregate_f<<<AGG_BLK, 256, 0, S>>>(x, Hb[p], m, rp[p], col[p]);
        k_gemm<true, false><<<gN512, 256, GEMM_DSMEM, S>>>(Hb[p], WT0, nullptr, Tb[p], nullptr, e0_bg, e0_bb, NN, 128, 512, sb + 0, p);
        k_gemm<true, true><<<gN256, 256, GEMM_DSMEM_BNA, S>>>(Tb[p], WT1, nullptr, Ub[p], scsh[p], nullptr, nullptr, NN, 512, 256, sb + 1, p);

        // encoder layer 1
        k_aggregate_b<false><<<AGG_BLK, 256, 0, S>>>(Ub[p], Hb[p], nullptr, e0_ng, e0_nb, rp[p], col[p], p);
        k_gemm<true, false><<<gN512, 256, GEMM_DSMEM, S>>>(Hb[p], WT2, nullptr, Tb[p], nullptr, e1_bg, e1_bb, NN, 256, 512, sb + 2, p);
        k_gemm<true, true><<<gN256, 256, GEMM_DSMEM_BNA, S>>>(Tb[p], WT3, nullptr, Ub[p], scsh[p], nullptr, nullptr, NN, 512, 256, sb + 3, p);

        // decoder
        k_aggregate_b<true><<<AGG_BLK, 256, 0, S>>>(Ub[p], Hb[p], m, e1_ng, e1_nb, rp[p], col[p], p);
        k_gemm<true, false><<<gN512, 256, GEMM_DSMEM, S>>>(Hb[p], WT4, nullptr, Tb[p], nullptr, d_bg, d_bb, NN, 256, 512, sb + 4, p);
        k_gemm<false, true><<<gN128, 256, GEMM_DSMEM_BNA, S>>>(Tb[p], WT5, Uf[p], nullptr, scsh[p], nullptr, nullptr, NN, 512, 128, sb + 5, p);
        k_bncos<<<1024, 256, 0, S>>>(Uf[p], RE[p], d_ng, d_nb, x, m, p, p * 2);
    }

    // ---- join ----
    cudaEventRecord(evJ0, st[0]);
    cudaEventRecord(evJ1, st[1]);
    cudaStreamWaitEvent(0, evJ0, 0);
    cudaStreamWaitEvent(0, evJ1, 0);

    k_cos<<<512, 256>>>(RE2, RE1, 4);
    k_finalize<<<1, 1>>>(out);
    (void)in_sizes; (void)n_in; (void)out_size;
}

// round 17
// speedup vs baseline: 1.0104x; 1.0104x over previous
#include <cuda_runtime.h>
#include <cuda_bf16.h>
#include <math.h>
#include <stdint.h>

#define NN    50000
#define MPAD  50048
#define NE    320000
#define D_IN  128
#define D_OUT 256
#define D_HID 512

// ---------------- scratch (per-pass duplicated; no allocation) ----------------
__device__ __nv_bfloat16 g_Xb[(size_t)NN * D_IN];      // bf16 copy of x (prelude)
__device__ __nv_bfloat16 g_Hb[2][(size_t)MPAD * D_OUT];
__device__ __nv_bfloat16 g_Tb[2][(size_t)MPAD * D_HID];
__device__ __nv_bfloat16 g_Ub[2][(size_t)MPAD * D_OUT];
__device__ float  g_RE1[(size_t)NN * D_IN];
__device__ float  g_RE2[(size_t)NN * D_IN];
__device__ __nv_bfloat16 g_WTb[655360];
__device__ double g_sum[12 * D_HID];     // single-use stat buffers (zeroed once/replay)
__device__ double g_sq [12 * D_HID];
__device__ float  g_mean[2 * D_HID];     // per-pass BN params
__device__ float  g_rstd[2 * D_HID];
__device__ float2 g_scsh[2][D_HID];      // per-pass combined (scale, shift) for GEMM-fused BN
__device__ double g_acc[8];

// per-pass CSR
__device__ int g_deg   [2][NN];
__device__ int g_rowptr[2][NN + 1];
__device__ int g_cursor[2][NN];
__device__ int g_col   [2][NE];

__device__ int g_mask_mode, g_ei_i64, g_cnt[8];

// ---------------- dtype detection ----------------
__global__ void k_zero_cnt() { if (threadIdx.x < 8) g_cnt[threadIdx.x] = 0; }

__global__ void k_detect(const unsigned char* __restrict__ mbytes,
                         const int* __restrict__ eints) {
    int i  = blockIdx.x * blockDim.x + threadIdx.x;
    int st = gridDim.x * blockDim.x;
    int c1 = 0, c3 = 0, ez = 0;
    for (int j = i; j < NN; j += st) {
        unsigned char v = mbytes[j];
        if (v && (j & 3) == 1) c1++;
        if (v && (j & 3) == 3) c3++;
    }
    for (int j = i; j < 100000; j += st)
        if ((j & 1) && eints[j] == 0) ez++;
    atomicAdd(&g_cnt[0], c1);
    atomicAdd(&g_cnt[1], c3);
    atomicAdd(&g_cnt[2], ez);
}

__global__ void k_detect_fin() {
    if (threadIdx.x == 0) {
        if      (g_cnt[1] > 1000) g_mask_mode = 2;
        else if (g_cnt[0] > 1000) g_mask_mode = 0;
        else                      g_mask_mode = 1;
        g_ei_i64 = (g_cnt[2] > 25000) ? 1 : 0;
    }
}

__device__ __forceinline__ bool mask_at(const void* __restrict__ m, int n) {
    int mode = g_mask_mode;
    if (mode == 0) return ((const unsigned char*)m)[n] != 0;
    if (mode == 1) return ((const int*)m)[n] != 0;
    return ((const float*)m)[n] != 0.f;
}

__device__ __forceinline__ int ei_at(const void* __restrict__ ei, long idx) {
    return g_ei_i64 ? (int)((const long long*)ei)[idx] : ((const int*)ei)[idx];
}

// ---------------- tiny utility kernels ----------------
__global__ void k_zero_acc() {
    if (threadIdx.x < 8 && blockIdx.x == 0) g_acc[threadIdx.x] = 0.0;
    int c  = blockIdx.x * blockDim.x + threadIdx.x;
    int st = gridDim.x * blockDim.x;
    for (int i = c; i < 12 * D_HID; i += st) { g_sum[i] = 0.0; g_sq[i] = 0.0; }
    int* dg = &g_deg[0][0];
    for (int i = c; i < 2 * NN; i += st) dg[i] = 0;
}

// ---------------- bf16 helpers ----------------
__device__ __forceinline__ uint32_t pack_bf16x2(float lo, float hi) {
    uint32_t r;
    asm("cvt.rn.bf16x2.f32 %0, %1, %2;" : "=r"(r) : "f"(hi), "f"(lo));
    return r;
}
__device__ __forceinline__ float bflo(uint32_t u) { return __uint_as_float(u << 16); }
__device__ __forceinline__ float bfhi(uint32_t u) { return __uint_as_float(u & 0xffff0000u); }

// convert x (fp32) -> bf16 copy (prelude, once per replay)
__global__ void k_x2b(const float* __restrict__ x, __nv_bfloat16* __restrict__ xb) {
    long i  = blockIdx.x * (long)blockDim.x + threadIdx.x;
    long st = (long)gridDim.x * blockDim.x;
    const long tot2 = (long)NN * D_IN / 2;
    const float2* xp = (const float2*)x;
    uint32_t* bp = (uint32_t*)xb;
    for (; i < tot2; i += st) {
        float2 v = xp[i];
        bp[i] = pack_bf16x2(v.x, v.y);
    }
}

// ---------------- weight transpose+convert: W[K][N] f32 -> WT[N][K] bf16 ----------------
__global__ void k_transpose(const float* __restrict__ W, __nv_bfloat16* __restrict__ WT,
                            int K, int N) {
    __shared__ float tile[32][33];
    int n0 = blockIdx.x * 32, k0 = blockIdx.y * 32;
    int tx = threadIdx.x, ty = threadIdx.y;
    #pragma unroll
    for (int i = 0; i < 4; i++)
        tile[ty + i * 8][tx] = W[(size_t)(k0 + ty + i * 8) * N + n0 + tx];
    __syncthreads();
    #pragma unroll
    for (int i = 0; i < 4; i++)
        WT[(size_t)(n0 + ty + i * 8) * K + k0 + tx] = __float2bfloat16(tile[tx][ty + i * 8]);
}

// ---------------- CSR build (parameterized per pass) ----------------
__global__ void k_count(const void* __restrict__ ei, int* __restrict__ deg) {
    int e  = blockIdx.x * blockDim.x + threadIdx.x;
    int st = gridDim.x * blockDim.x;
    for (; e < NE; e += st)
        atomicAdd(&deg[ei_at(ei, (long)NE + e)], 1);
}

__global__ void __launch_bounds__(1024) k_scan(const int* __restrict__ deg,
                                               int* __restrict__ rowptr,
                                               int* __restrict__ cursor) {
    __shared__ int ssum[1024];
    const int t = threadIdx.x;
    const int C = (NN + 1023) / 1024;
    int lo = t * C, hi = min(NN, lo + C);
    int s = 0;
    for (int i = lo; i < hi; i++) s += deg[i];
    ssum[t] = s;
    __syncthreads();
    #pragma unroll
    for (int o = 1; o < 1024; o <<= 1) {
        int v = (t >= o) ? ssum[t - o] : 0;
        __syncthreads();
        ssum[t] += v;
        __syncthreads();
    }
    int run = (t == 0) ? 0 : ssum[t - 1];
    for (int i = lo; i < hi; i++) {
        int d = deg[i];
        rowptr[i] = run;
        cursor[i] = run;
        run += d;
    }
    if (t == 1023) rowptr[NN] = run;
}

__global__ void k_fill(const void* __restrict__ ei, int* __restrict__ cursor,
                       int* __restrict__ col) {
    int e  = blockIdx.x * blockDim.x + threadIdx.x;
    int st = gridDim.x * blockDim.x;
    for (; e < NE; e += st) {
        int s = ei_at(ei, e);
        int d = ei_at(ei, (long)NE + e);
        int slot = atomicAdd(&cursor[d], 1);
        col[slot] = s;
    }
}

// ---- bf16-input CSR aggregate (layer 0): D=128, masked -> bf16 out ----
__global__ void k_aggregate_f(const __nv_bfloat16* __restrict__ in, __nv_bfloat16* __restrict__ hb,
                              const void* __restrict__ m,
                              const int* __restrict__ rowptr, const int* __restrict__ col) {
    const int gtid = blockIdx.x * blockDim.x + threadIdx.x;
    const int warp = gtid >> 5;
    const int lane = gtid & 31;
    if (warp >= NN) return;
    const uint2* ip = (const uint2*)in;   // 4 bf16 per uint2; 32 lanes = 128 cols

    float a0 = 0.f, a1 = 0.f, a2 = 0.f, a3 = 0.f;
    auto consume = [&](uint2 u) {
        a0 += bflo(u.x); a1 += bfhi(u.x);
        a2 += bflo(u.y); a3 += bfhi(u.y);
    };

    if (!mask_at(m, warp)) consume(ip[(size_t)warp * 32 + lane]);

    int j   = rowptr[warp];
    int end = rowptr[warp + 1];
    for (; j < end; j += 4) {
        int cnt = end - j;
        int idx[4]; bool ok[4];
        #pragma unroll
        for (int t = 0; t < 4; t++) {
            idx[t] = (t < cnt) ? __ldg(&col[j + t]) : 0;
            ok[t]  = (t < cnt) && !mask_at(m, idx[t]);
        }
        uint2 v[4];
        #pragma unroll
        for (int t = 0; t < 4; t++)
            if (ok[t]) v[t] = __ldg(&ip[(size_t)idx[t] * 32 + lane]);
        #pragma unroll
        for (int t = 0; t < 4; t++)
            if (ok[t]) consume(v[t]);
    }
    uint2* hp = (uint2*)hb;
    hp[(size_t)warp * 32 + lane] = make_uint2(pack_bf16x2(a0, a1), pack_bf16x2(a2, a3));
}

// ---- bf16-input CSR aggregate: D=256, fused BN+ReLU (per-pass mean/rstd), opt mask ----
template <bool MASKED>
__global__ void k_aggregate_b(const __nv_bfloat16* __restrict__ in, __nv_bfloat16* __restrict__ hb,
                              const void* __restrict__ m,
                              const float* __restrict__ gg, const float* __restrict__ bb,
                              const int* __restrict__ rowptr, const int* __restrict__ col,
                              int pass) {
    const int gtid = blockIdx.x * blockDim.x + threadIdx.x;
    const int warp = gtid >> 5;
    const int lane = gtid & 31;
    if (warp >= NN) return;
    const uint4* ip = (const uint4*)in;
    const int mo = pass * D_HID;

    float sc[8], sh[8];
    #pragma unroll
    for (int i = 0; i < 8; i++) {
        int ch = lane * 8 + i;
        sc[i] = g_rstd[mo + ch] * __ldg(&gg[ch]);
        sh[i] = __ldg(&bb[ch]) - g_mean[mo + ch] * sc[i];
    }

    float a[8];
    #pragma unroll
    for (int i = 0; i < 8; i++) a[i] = 0.f;

    auto consume = [&](uint4 u) {
        float f[8];
        f[0] = bflo(u.x); f[1] = bfhi(u.x);
        f[2] = bflo(u.y); f[3] = bfhi(u.y);
        f[4] = bflo(u.z); f[5] = bfhi(u.z);
        f[6] = bflo(u.w); f[7] = bfhi(u.w);
        #pragma unroll
        for (int i = 0; i < 8; i++)
            a[i] += fmaxf(f[i] * sc[i] + sh[i], 0.f);
    };

    if (!(MASKED && mask_at(m, warp)))
        consume(ip[(size_t)warp * 32 + lane]);

    int j   = rowptr[warp];
    int end = rowptr[warp + 1];
    for (; j < end; j += 4) {
        int cnt = end - j;
        int idx[4]; bool ok[4];
        #pragma unroll
        for (int t = 0; t < 4; t++) {
            idx[t] = (t < cnt) ? __ldg(&col[j + t]) : 0;
            ok[t]  = (t < cnt) && (!MASKED || !mask_at(m, idx[t]));
        }
        uint4 v[4];
        #pragma unroll
        for (int t = 0; t < 4; t++)
            if (ok[t]) v[t] = __ldg(&ip[(size_t)idx[t] * 32 + lane]);
        #pragma unroll
        for (int t = 0; t < 4; t++)
            if (ok[t]) consume(v[t]);
    }

    uint4* hp = (uint4*)hb;
    hp[(size_t)warp * 32 + lane] = make_uint4(
        pack_bf16x2(a[0], a[1]), pack_bf16x2(a[2], a[3]),
        pack_bf16x2(a[4], a[5]), pack_bf16x2(a[6], a[7]));
}

// ---------------- cp.async helpers ----------------
__device__ __forceinline__ void cp_async16(uint32_t dst, const void* src) {
    asm volatile("cp.async.cg.shared.global [%0], [%1], 16;" :: "r"(dst), "l"(src));
}
__device__ __forceinline__ void cp_commit() { asm volatile("cp.async.commit_group;"); }
template <int W> __device__ __forceinline__ void cp_wait() {
    asm volatile("cp.async.wait_group %0;" :: "n"(W));
}

// ---------------- bf16 mma + ldmatrix ----------------
__device__ __forceinline__ void mma_bf16(float* d, const uint32_t* a, const uint32_t* b) {
    asm volatile(
        "mma.sync.aligned.m16n8k16.row.col.f32.bf16.bf16.f32 "
        "{%0,%1,%2,%3}, {%4,%5,%6,%7}, {%8,%9}, {%0,%1,%2,%3};"
        : "+f"(d[0]), "+f"(d[1]), "+f"(d[2]), "+f"(d[3])
        : "r"(a[0]), "r"(a[1]), "r"(a[2]), "r"(a[3]), "r"(b[0]), "r"(b[1]));
}

__device__ __forceinline__ void ldsm4(uint32_t* r, uint32_t addr) {
    asm volatile("ldmatrix.sync.aligned.m8n8.x4.shared.b16 {%0,%1,%2,%3}, [%4];"
        : "=r"(r[0]), "=r"(r[1]), "=r"(r[2]), "=r"(r[3]) : "r"(addr));
}

// ---------------- 3-stage pipelined bf16 GEMM (128x128, ldmatrix, opt fused BN on A) ----
#define SW 20
#define BUFW (128 * SW)
#define GEMM_DSMEM      (3 * 2 * BUFW * 4)            // 61440 bytes
#define GEMM_DSMEM_BNA  (GEMM_DSMEM + 4096)           // + scale/shift table

template <bool BNA>
__global__ void __launch_bounds__(256)
k_gemm(const __nv_bfloat16* __restrict__ A, const __nv_bfloat16* __restrict__ Bt,
       __nv_bfloat16* __restrict__ Cb,
       const float2* __restrict__ scsh,
       int M, int K, int N, int sbuf) {
    extern __shared__ uint32_t dsm[];
    const uint32_t sbase = (uint32_t)__cvta_generic_to_shared(dsm);
    float2* s_scsh = (float2*)((char*)dsm + GEMM_DSMEM);

    const int tid  = threadIdx.x;
    const int lane = tid & 31;
    const int warp = tid >> 5;
    const int wm   = warp & 3;
    const int wn   = warp >> 2;
    const int gid  = lane >> 2;
    const int tq   = lane & 3;
    const int brow = blockIdx.y * 128;
    const int bcol = blockIdx.x * 128;

    if (BNA) {
        s_scsh[tid]       = scsh[tid];
        s_scsh[tid + 256] = scsh[tid + 256];
    }

    const int tIdx = lane >> 3;
    const int trow = lane & 7;
    uint32_t aoff[2];
    #pragma unroll
    for (int mt = 0; mt < 2; mt++) {
        int row  = wm * 32 + mt * 16 + (tIdx & 1) * 8 + trow;
        int word = (tIdx >> 1) * 4;
        aoff[mt] = (uint32_t)(row * SW + word) * 4;
    }
    uint32_t boff[4];
    #pragma unroll
    for (int j = 0; j < 4; j++) {
        int nt   = 2 * j + (tIdx >> 1);
        int row  = wn * 64 + nt * 8 + trow;
        int word = (tIdx & 1) * 4;
        boff[j]  = (uint32_t)(row * SW + word) * 4;
    }

    float acc[2][8][4];
    #pragma unroll
    for (int i = 0; i < 2; i++)
        #pragma unroll
        for (int j = 0; j < 8; j++)
            #pragma unroll
            for (int q = 0; q < 4; q++) acc[i][j][q] = 0.f;

    const int nch = K >> 5;

    auto fill = [&](int s, int k0) {
        uint32_t abase = sbase + (uint32_t)(s * 2 * BUFW) * 4;
        uint32_t bbase = abase + (uint32_t)BUFW * 4;
        #pragma unroll
        for (int i = 0; i < 2; i++) {
            int idx = tid + i * 256;
            int row = idx >> 2;
            int c16 = idx & 3;
            uint32_t doff = (uint32_t)(row * SW + c16 * 4) * 4;
            cp_async16(abase + doff, A  + (size_t)(brow + row) * K + k0 + c16 * 8);
            cp_async16(bbase + doff, Bt + (size_t)(bcol + row) * K + k0 + c16 * 8);
        }
    };

    fill(0, 0);  cp_commit();
    fill(1, 32); cp_commit();

    for (int c = 0; c < nch; c++) {
        if (c < nch - 1) cp_wait<1>(); else cp_wait<0>();
        __syncthreads();
        if (c + 2 < nch) { fill((c + 2) % 3, (c + 2) << 5); cp_commit(); }

        const uint32_t sA = sbase + (uint32_t)((c % 3) * 2 * BUFW) * 4;
        const uint32_t sB = sA + (uint32_t)BUFW * 4;
        #pragma unroll
        for (int kw = 0; kw < 16; kw += 8) {
            uint32_t a[2][4], bt[4][4];
            ldsm4(a[0], sA + aoff[0] + kw * 4);
            ldsm4(a[1], sA + aoff[1] + kw * 4);
            #pragma unroll
            for (int j = 0; j < 4; j++)
                ldsm4(bt[j], sB + boff[j] + kw * 4);

            if (BNA) {
                int cb = (c << 5) + 2 * kw + 2 * tq;
                float4 p0 = *(const float4*)&s_scsh[cb];
                float4 p1 = *(const float4*)&s_scsh[cb + 8];
                #pragma unroll
                for (int mt = 0; mt < 2; mt++) {
                    #pragma unroll
                    for (int q = 0; q < 4; q++) {
                        float4 p = (q < 2) ? p0 : p1;
                        uint32_t r = a[mt][q];
                        float lo = fmaxf(bflo(r) * p.x + p.y, 0.f);
                        float hi = fmaxf(bfhi(r) * p.z + p.w, 0.f);
                        a[mt][q] = pack_bf16x2(lo, hi);
                    }
                }
            }

            #pragma unroll
            for (int mt = 0; mt < 2; mt++)
                #pragma unroll
                for (int j = 0; j < 4; j++) {
                    mma_bf16(acc[mt][2 * j],     a[mt], &bt[j][0]);
                    mma_bf16(acc[mt][2 * j + 1], a[mt], &bt[j][2]);
                }
        }
        __syncthreads();
    }

    // ---- store C (bf16) ----
    #pragma unroll
    for (int mt = 0; mt < 2; mt++) {
        int r0 = brow + wm * 32 + mt * 16 + gid;
        int r1 = r0 + 8;
        #pragma unroll
        for (int nt = 0; nt < 8; nt++) {
            int c = bcol + wn * 64 + nt * 8 + tq * 2;
            if (r0 < M)
                *(uint32_t*)(Cb + (size_t)r0 * N + c) = pack_bf16x2(acc[mt][nt][0], acc[mt][nt][1]);
            if (r1 < M)
                *(uint32_t*)(Cb + (size_t)r1 * N + c) = pack_bf16x2(acc[mt][nt][2], acc[mt][nt][3]);
        }
    }

    // ---- column stats -> buffer sbuf ----
    float csum[16], csq[16];
    #pragma unroll
    for (int nt = 0; nt < 8; nt++) {
        float s0 = 0.f, s1 = 0.f, q0 = 0.f, q1 = 0.f;
        #pragma unroll
        for (int mt = 0; mt < 2; mt++) {
            int r0 = brow + wm * 32 + mt * 16 + gid;
            int r1 = r0 + 8;
            if (r0 < M) {
                float a = acc[mt][nt][0], b = acc[mt][nt][1];
                s0 += a; q0 += a * a; s1 += b; q1 += b * b;
            }
            if (r1 < M) {
                float a = acc[mt][nt][2], b = acc[mt][nt][3];
                s0 += a; q0 += a * a; s1 += b; q1 += b * b;
            }
        }
        csum[nt * 2] = s0; csum[nt * 2 + 1] = s1;
        csq [nt * 2] = q0; csq [nt * 2 + 1] = q1;
    }
    #pragma unroll
    for (int o = 4; o <= 16; o <<= 1) {
        #pragma unroll
        for (int p = 0; p < 16; p++) {
            csum[p] += __shfl_xor_sync(0xffffffffu, csum[p], o);
            csq[p]  += __shfl_xor_sync(0xffffffffu, csq[p],  o);
        }
    }
    float* s_ps = (float*)dsm;
    float* s_pq = s_ps + 512;
    __syncthreads();
    if (gid == 0) {
        #pragma unroll
        for (int nt = 0; nt < 8; nt++) {
            int lc = wn * 64 + nt * 8 + tq * 2;
            s_ps[wm * 128 + lc]     = csum[nt * 2];
            s_ps[wm * 128 + lc + 1] = csum[nt * 2 + 1];
            s_pq[wm * 128 + lc]     = csq[nt * 2];
            s_pq[wm * 128 + lc + 1] = csq[nt * 2 + 1];
        }
    }
    __syncthreads();
    if (tid < 128) {
        float ts = s_ps[tid] + s_ps[128 + tid] + s_ps[256 + tid] + s_ps[384 + tid];
        float tg = s_pq[tid] + s_pq[128 + tid] + s_pq[256 + tid] + s_pq[384 + tid];
        atomicAdd(&g_sum[sbuf * D_HID + bcol + tid], (double)ts);
        atomicAdd(&g_sq [sbuf * D_HID + bcol + tid], (double)tg);
    }
}

// mean/rstd from stat buffer sbuf -> per-pass g_mean/g_rstd (+ optional scsh table)
__global__ void k_bn_fin(int sbuf, int C, int pass,
                         const float* __restrict__ gg, const float* __restrict__ bb) {
    int c = threadIdx.x;
    if (c < C) {
        double mu  = g_sum[sbuf * D_HID + c] / NN;
        double var = g_sq [sbuf * D_HID + c] / NN - mu * mu;
        if (var < 0.0) var = 0.0;
        float rs = (float)rsqrt(var + 1e-5);
        float mf = (float)mu;
        g_mean[pass * D_HID + c] = mf;
        g_rstd[pass * D_HID + c] = rs;
        if (gg) {
            float s = rs * gg[c];
            g_scsh[pass][c] = make_float2(s, bb[c] - mf * s);
        }
    } else if (c < D_HID && gg) {
        g_scsh[pass][c] = make_float2(0.f, 0.f);   // pad channels
    }
}

// ---- fused decoder epilogue: RE = relu(bn(Ub)); masked 1-cos(RE, x) -> g_acc ----
// Ub is bf16 [NN][128]; x stays fp32.
__global__ void k_bncos(const __nv_bfloat16* __restrict__ U, float* __restrict__ RE,
                        const float* __restrict__ gg, const float* __restrict__ bb,
                        const float* __restrict__ x, const void* __restrict__ m,
                        int pass, int accOff) {
    int gtid = blockIdx.x * blockDim.x + threadIdx.x;
    int warp = gtid >> 5, lane = gtid & 31;
    int nw   = (gridDim.x * blockDim.x) >> 5;
    const int mo = pass * D_HID;
    const uint2* up = (const uint2*)U;

    int ch = lane * 4;
    float4 sc, sh;
    sc.x = g_rstd[mo+ch+0] * __ldg(&gg[ch+0]); sh.x = __ldg(&bb[ch+0]) - g_mean[mo+ch+0]*sc.x;
    sc.y = g_rstd[mo+ch+1] * __ldg(&gg[ch+1]); sh.y = __ldg(&bb[ch+1]) - g_mean[mo+ch+1]*sc.y;
    sc.z = g_rstd[mo+ch+2] * __ldg(&gg[ch+2]); sh.z = __ldg(&bb[ch+2]) - g_mean[mo+ch+2]*sc.z;
    sc.w = g_rstd[mo+ch+3] * __ldg(&gg[ch+3]); sh.w = __ldg(&bb[ch+3]) - g_mean[mo+ch+3]*sc.w;

    double ls = 0.0, lc = 0.0;
    for (int n = warp; n < NN; n += nw) {
        uint2 ub = up[(size_t)n * 32 + lane];
        float4 v;
        v.x = fmaxf(bflo(ub.x) * sc.x + sh.x, 0.f);
        v.y = fmaxf(bfhi(ub.x) * sc.y + sh.y, 0.f);
        v.z = fmaxf(bflo(ub.y) * sc.z + sh.z, 0.f);
        v.w = fmaxf(bfhi(ub.y) * sc.w + sh.w, 0.f);
        *((float4*)(RE + (size_t)n * 128) + lane) = v;

        if (mask_at(m, n)) {
            float4 vb = *((const float4*)(x + (size_t)n * 128) + lane);
            float dot = v.x*vb.x + v.y*vb.y + v.z*vb.z + v.w*vb.w;
            float na  = v.x*v.x + v.y*v.y + v.z*v.z + v.w*v.w;
            float nb  = vb.x*vb.x + vb.y*vb.y + vb.z*vb.z + vb.w*vb.w;
            #pragma unroll
            for (int o = 16; o; o >>= 1) {
                dot += __shfl_xor_sync(0xffffffffu, dot, o);
                na  += __shfl_xor_sync(0xffffffffu, na,  o);
                nb  += __shfl_xor_sync(0xffffffffu, nb,  o);
            }
            if (lane == 0) {
                float cs = dot / (fmaxf(sqrtf(na), 1e-12f) * fmaxf(sqrtf(nb), 1e-12f));
                ls += 1.0 - (double)cs;
                lc += 1.0;
            }
        }
    }
    if (lane == 0 && lc > 0.0) {
        atomicAdd(&g_acc[accOff], ls);
        atomicAdd(&g_acc[accOff + 1], lc);
    }
}

// ---------------- contrastive cosine (all nodes) ----------------
__global__ void k_cos(const float* __restrict__ a, const float* __restrict__ b,
                      int accOff) {
    int gtid = blockIdx.x * blockDim.x + threadIdx.x;
    int warp = gtid >> 5, lane = gtid & 31;
    int nw   = (gridDim.x * blockDim.x) >> 5;
    double ls = 0.0;
    for (int n = warp; n < NN; n += nw) {
        float4 va = *((const float4*)(a + (size_t)n * 128) + lane);
        float4 vb = *((const float4*)(b + (size_t)n * 128) + lane);
        float dot = va.x*vb.x + va.y*vb.y + va.z*vb.z + va.w*vb.w;
        float na  = va.x*va.x + va.y*va.y + va.z*va.z + va.w*va.w;
        float nb  = vb.x*vb.x + vb.y*vb.y + vb.z*vb.z + vb.w*vb.w;
        #pragma unroll
        for (int o = 16; o; o >>= 1) {
            dot += __shfl_xor_sync(0xffffffffu, dot, o);
            na  += __shfl_xor_sync(0xffffffffu, na,  o);
            nb  += __shfl_xor_sync(0xffffffffu, nb,  o);
        }
        if (lane == 0) {
            float cs = dot / (fmaxf(sqrtf(na), 1e-12f) * fmaxf(sqrtf(nb), 1e-12f));
            ls += 1.0 - (double)cs;
        }
    }
    if (lane == 0) atomicAdd(&g_acc[accOff], ls);
}

__global__ void k_finalize(float* out) {
    double v = g_acc[0] / g_acc[1] + g_acc[2] / g_acc[3] + 0.1 * (g_acc[4] / (double)NN);
    out[0] = (float)v;
}

// ---------------- host-side orchestration ----------------
extern "C" void kernel_launch(void* const* d_in, const int* in_sizes, int n_in,
                              void* d_out, int out_size) {
    const float* x   = (const float*)d_in[0];
    const void*  eis[2] = { d_in[1], d_in[2] };
    const void*  ms [2] = { d_in[3], d_in[4] };
    const float* e0_w1 = (const float*)d_in[6];
    const float* e0_w2 = (const float*)d_in[7];
    const float* e0_bg = (const float*)d_in[8];
    const float* e0_bb = (const float*)d_in[9];
    const float* e0_ng = (const float*)d_in[10];
    const float* e0_nb = (const float*)d_in[11];
    const float* e1_w1 = (const float*)d_in[12];
    const float* e1_w2 = (const float*)d_in[13];
    const float* e1_bg = (const float*)d_in[14];
    const float* e1_bb = (const float*)d_in[15];
    const float* e1_ng = (const float*)d_in[16];
    const float* e1_nb = (const float*)d_in[17];
    const float* d_w1  = (const float*)d_in[18];
    const float* d_w2  = (const float*)d_in[19];
    const float* d_bg  = (const float*)d_in[20];
    const float* d_bb  = (const float*)d_in[21];
    const float* d_ng  = (const float*)d_in[22];
    const float* d_nb  = (const float*)d_in[23];
    float* out = (float*)d_out;

    __nv_bfloat16 *Xb, *Hb0, *Tb0, *Ub0, *WTb;
    float *RE1, *RE2;
    float2* scsh0;
    int *deg0, *rp0, *cur0, *col0;
    cudaGetSymbolAddress((void**)&Xb,  g_Xb);
    cudaGetSymbolAddress((void**)&Hb0, g_Hb);
    cudaGetSymbolAddress((void**)&Tb0, g_Tb);
    cudaGetSymbolAddress((void**)&Ub0, g_Ub);
    cudaGetSymbolAddress((void**)&WTb, g_WTb);
    cudaGetSymbolAddress((void**)&RE1, g_RE1);
    cudaGetSymbolAddress((void**)&RE2, g_RE2);
    cudaGetSymbolAddress((void**)&scsh0, g_scsh);
    cudaGetSymbolAddress((void**)&deg0, g_deg);
    cudaGetSymbolAddress((void**)&rp0,  g_rowptr);
    cudaGetSymbolAddress((void**)&cur0, g_cursor);
    cudaGetSymbolAddress((void**)&col0, g_col);

    __nv_bfloat16* Hb[2] = { Hb0, Hb0 + (size_t)MPAD * D_OUT };
    __nv_bfloat16* Tb[2] = { Tb0, Tb0 + (size_t)MPAD * D_HID };
    __nv_bfloat16* Ub[2] = { Ub0, Ub0 + (size_t)MPAD * D_OUT };
    float*         RE[2] = { RE1, RE2 };
    float2*      scsh[2] = { scsh0, scsh0 + D_HID };
    int* deg[2] = { deg0, deg0 + NN };
    int* rp [2] = { rp0,  rp0 + NN + 1 };
    int* cur[2] = { cur0, cur0 + NN };
    int* col[2] = { col0, col0 + NE };

    __nv_bfloat16* WT0 = WTb;
    __nv_bfloat16* WT1 = WTb + 65536;
    __nv_bfloat16* WT2 = WTb + 196608;
    __nv_bfloat16* WT3 = WTb + 327680;
    __nv_bfloat16* WT4 = WTb + 458752;
    __nv_bfloat16* WT5 = WTb + 589824;

    static cudaStream_t st[2] = { nullptr, nullptr };
    static cudaEvent_t  evR = nullptr, evJ0 = nullptr, evJ1 = nullptr;
    if (!st[0]) {
        cudaStreamCreateWithFlags(&st[0], cudaStreamNonBlocking);
        cudaStreamCreateWithFlags(&st[1], cudaStreamNonBlocking);
        cudaEventCreateWithFlags(&evR,  cudaEventDisableTiming);
        cudaEventCreateWithFlags(&evJ0, cudaEventDisableTiming);
        cudaEventCreateWithFlags(&evJ1, cudaEventDisableTiming);
        cudaFuncSetAttribute(k_gemm<false>, cudaFuncAttributeMaxDynamicSharedMemorySize, GEMM_DSMEM);
        cudaFuncSetAttribute(k_gemm<true>,  cudaFuncAttributeMaxDynamicSharedMemorySize, GEMM_DSMEM_BNA);
    }

    // ---- prelude on default stream ----
    k_zero_cnt<<<1, 32>>>();
    k_detect<<<128, 256>>>((const unsigned char*)ms[0], (const int*)eis[0]);
    k_detect_fin<<<1, 32>>>();
    k_zero_acc<<<48, 256>>>();
    k_x2b<<<2048, 256>>>(x, Xb);

    dim3 tb(32, 8);
    k_transpose<<<dim3(512/32, 128/32), tb>>>(e0_w1, WT0, 128, 512);
    k_transpose<<<dim3(256/32, 512/32), tb>>>(e0_w2, WT1, 512, 256);
    k_transpose<<<dim3(512/32, 256/32), tb>>>(e1_w1, WT2, 256, 512);
    k_transpose<<<dim3(256/32, 512/32), tb>>>(e1_w2, WT3, 512, 256);
    k_transpose<<<dim3(512/32, 256/32), tb>>>(d_w1,  WT4, 256, 512);
    k_transpose<<<dim3(128/32, 512/32), tb>>>(d_w2,  WT5, 512, 128);

    // ---- fork ----
    cudaEventRecord(evR, 0);
    cudaStreamWaitEvent(st[0], evR, 0);
    cudaStreamWaitEvent(st[1], evR, 0);

    const int AGG_BLK = (NN * 32 + 255) / 256;
    const dim3 gN512(4, MPAD / 128);
    const dim3 gN256(2, MPAD / 128);
    const dim3 gN128(1, MPAD / 128);

    for (int p = 0; p < 2; p++) {
        cudaStream_t S = st[p];
        const void* ei = eis[p];
        const void* m  = ms[p];
        const int   sb = p * 6;

        k_count<<<1024, 256, 0, S>>>(ei, deg[p]);
        k_scan<<<1, 1024, 0, S>>>(deg[p], rp[p], cur[p]);
        k_fill<<<1024, 256, 0, S>>>(ei, cur[p], col[p]);

        // encoder layer 0
        k_aggregate_f<<<AGG_BLK, 256, 0, S>>>(Xb, Hb[p], m, rp[p], col[p]);
        k_gemm<false><<<gN512, 256, GEMM_DSMEM, S>>>(Hb[p], WT0, Tb[p], nullptr, NN, 128, 512, sb + 0);
        k_bn_fin<<<1, 512, 0, S>>>(sb + 0, 512, p, e0_bg, e0_bb);
        k_gemm<true><<<gN256, 256, GEMM_DSMEM_BNA, S>>>(Tb[p], WT1, Ub[p], scsh[p], NN, 512, 256, sb + 1);
        k_bn_fin<<<1, 512, 0, S>>>(sb + 1, 256, p, nullptr, nullptr);

        // encoder layer 1
        k_aggregate_b<false><<<AGG_BLK, 256, 0, S>>>(Ub[p], Hb[p], nullptr, e0_ng, e0_nb, rp[p], col[p], p);
        k_gemm<false><<<gN512, 256, GEMM_DSMEM, S>>>(Hb[p], WT2, Tb[p], nullptr, NN, 256, 512, sb + 2);
        k_bn_fin<<<1, 512, 0, S>>>(sb + 2, 512, p, e1_bg, e1_bb);
        k_gemm<true><<<gN256, 256, GEMM_DSMEM_BNA, S>>>(Tb[p], WT3, Ub[p], scsh[p], NN, 512, 256, sb + 3);
        k_bn_fin<<<1, 512, 0, S>>>(sb + 3, 256, p, nullptr, nullptr);

        // decoder (GEMM2 writes bf16 into Ub; bncos reads bf16)
        k_aggregate_b<true><<<AGG_BLK, 256, 0, S>>>(Ub[p], Hb[p], m, e1_ng, e1_nb, rp[p], col[p], p);
        k_gemm<false><<<gN512, 256, GEMM_DSMEM, S>>>(Hb[p], WT4, Tb[p], nullptr, NN, 256, 512, sb + 4);
        k_bn_fin<<<1, 512, 0, S>>>(sb + 4, 512, p, d_bg, d_bb);
        k_gemm<true><<<gN128, 256, GEMM_DSMEM_BNA, S>>>(Tb[p], WT5, Ub[p], scsh[p], NN, 512, 128, sb + 5);
        k_bn_fin<<<1, 512, 0, S>>>(sb + 5, 128, p, nullptr, nullptr);
        k_bncos<<<1024, 256, 0, S>>>(Ub[p], RE[p], d_ng, d_nb, x, m, p, p * 2);
    }

    // ---- join ----
    cudaEventRecord(evJ0, st[0]);
    cudaEventRecord(evJ1, st[1]);
    cudaStreamWaitEvent(0, evJ0, 0);
    cudaStreamWaitEvent(0, evJ1, 0);

    k_cos<<<512, 256>>>(RE2, RE1, 4);
    k_finalize<<<1, 1>>>(out);
    (void)in_sizes; (void)n_in; (void)out_size;
}